// round 1
// baseline (speedup 1.0000x reference)
#include <cuda_runtime.h>
#include <cuda_bf16.h>

#define DD 96
#define NSEG 50
#define NT 301
#define BATCH 256
#define OUTW 4656   // 96 + 96*95/2

// One block per (batch, segment). Segment s covers time indices [6s, 6s+6].
// y[t-1][d] = p_t[d] - p_0[d] for t=1..6 staged in shared memory.
// A[i,j] = 0.5 * sum_{t=1..5} ( y_t[i]*y_{t+1}[j] - y_{t+1}[i]*y_t[j] )
// Output row per (b,s): [ lvl1 (=y_6, 96 floats) | triu pairs row-major (4560) ]
__global__ __launch_bounds__(256)
void logsig_kernel(const float* __restrict__ inp, float* __restrict__ out)
{
    const int bs = blockIdx.x;
    const int b  = bs / NSEG;
    const int s  = bs - b * NSEG;
    const float* __restrict__ p = inp + ((size_t)b * NT + 6 * s) * DD;

    __shared__ float y[6][DD];
    __shared__ float p0s[DD];

    const int tid = threadIdx.x;

    if (tid < DD) p0s[tid] = p[tid];
    __syncthreads();

    // build y: 6*96 = 576 elements, 256 threads
    for (int e = tid; e < 6 * DD; e += 256) {
        int t = e / DD;
        int d = e - t * DD;
        y[t][d] = p[(t + 1) * DD + d] - p0s[d];
    }
    __syncthreads();

    float* __restrict__ o = out + (size_t)bs * OUTW;

    // level-1 term
    if (tid < DD) o[tid] = y[5][tid];

    const int warp = tid >> 5;
    const int lane = tid & 31;

    // 95 pair-rows grouped 4 at a time -> 24 groups. Warp w takes groups
    // w, w+8, w+16 (tile counts 3/2/1 per group band -> 6 j-tiles per warp,
    // perfectly balanced).
    for (int g = warp; g < 24; g += 8) {
        const int i0 = 4 * g;

        // broadcast-load the 4 row vectors into registers (reused across tiles)
        float yi[4][6];
        #pragma unroll
        for (int r = 0; r < 4; r++) {
            #pragma unroll
            for (int t = 0; t < 6; t++)
                yi[r][t] = y[t][i0 + r];
        }

        const int jt0 = (i0 + 1) >> 5;   // first 32-aligned j-tile touching j > i0
        for (int jt = jt0; jt < 3; jt++) {
            const int j = (jt << 5) + lane;

            float yj[6];
            #pragma unroll
            for (int t = 0; t < 6; t++) yj[t] = y[t][j];

            #pragma unroll
            for (int r = 0; r < 4; r++) {
                const int i = i0 + r;
                float a = 0.0f;
                #pragma unroll
                for (int t = 0; t < 5; t++)
                    a += yi[r][t] * yj[t + 1] - yi[r][t + 1] * yj[t];

                if (j > i) {   // i can reach 95 in the last group: j>i then never fires
                    const int rowoff = i * 95 - ((i * (i - 1)) >> 1);
                    o[DD + rowoff + (j - i - 1)] = 0.5f * a;
                }
            }
        }
    }
}

extern "C" void kernel_launch(void* const* d_in, const int* in_sizes, int n_in,
                              void* d_out, int out_size)
{
    const float* inp = (const float*)d_in[0];
    float* out = (float*)d_out;
    logsig_kernel<<<BATCH * NSEG, 256>>>(inp, out);
}

// round 2
// speedup vs baseline: 1.4104x; 1.4104x over previous
#include <cuda_runtime.h>
#include <cuda_bf16.h>

#define DD 96
#define NSEG 50
#define NT 301
#define BATCH 256
#define OUTW 4656   // 96 + 96*95/2

// ---- Youla decomposition constants for the 6x6 antisymmetric tridiagonal form ----
// sin/cos(k*pi/7)
#define S1d 0.4338837391175581204757683328483
#define S2d 0.7818314824680298087084445266741
#define S3d 0.9749279121818236070181316829939
#define C1d 0.9009688679024191262361023195074
#define C2d 0.6234898018587335305250048840042
#define C3d 0.2225209339563144042889025644968
// P_k = (cos(k pi/7)/1.75) * ( a_k[2]*y2 + a_k[4]*y4 + a_k[6]*y6 ),  a=(-sin2t,+sin4t,-sin6t)
// Q_k =                       ( b_k[1]*y1 + b_k[3]*y3 + b_k[5]*y5 ),  b=(+sin t,-sin3t,+sin5t)
// A[i,j] = sum_k P_k[i] Q_k[j] - Q_k[i] P_k[j]
__device__ __constant__ float PA[3][3] = {
    { (float)(-(C1d/1.75)*S2d), (float)( (C1d/1.75)*S3d), (float)(-(C1d/1.75)*S1d) },
    { (float)(-(C2d/1.75)*S3d), (float)(-(C2d/1.75)*S1d), (float)( (C2d/1.75)*S2d) },
    { (float)(-(C3d/1.75)*S1d), (float)(-(C3d/1.75)*S2d), (float)(-(C3d/1.75)*S3d) },
};
__device__ __constant__ float QB[3][3] = {
    { (float)( S1d), (float)(-S3d), (float)( S2d) },
    { (float)( S2d), (float)(-S1d), (float)(-S3d) },
    { (float)( S3d), (float)( S2d), (float)( S1d) },
};

// ---- packed f32x2 helpers ----
__device__ __forceinline__ unsigned long long pack2(float lo, float hi) {
    unsigned long long r;
    asm("mov.b64 %0, {%1, %2};" : "=l"(r) : "f"(lo), "f"(hi));
    return r;
}
__device__ __forceinline__ unsigned long long fma2(unsigned long long a, unsigned long long b,
                                                   unsigned long long c) {
    unsigned long long d;
    asm("fma.rn.f32x2 %0, %1, %2, %3;" : "=l"(d) : "l"(a), "l"(b), "l"(c));
    return d;
}
__device__ __forceinline__ unsigned long long mul2(unsigned long long a, unsigned long long b) {
    unsigned long long d;
    asm("mul.rn.f32x2 %0, %1, %2;" : "=l"(d) : "l"(a), "l"(b));
    return d;
}
__device__ __forceinline__ void unpack2(unsigned long long v, float& lo, float& hi) {
    asm("mov.b64 {%0, %1}, %2;" : "=f"(lo), "=f"(hi) : "l"(v));
}

__global__ __launch_bounds__(256)
void logsig_kernel(const float* __restrict__ inp, float* __restrict__ out)
{
    const int bs = blockIdx.x;
    const int b  = bs / NSEG;
    const int s  = bs - b * NSEG;
    const float* __restrict__ p = inp + ((size_t)b * NT + 6 * s) * DD;
    float* __restrict__ o = out + (size_t)bs * OUTW;

    __shared__ float Ps[3][DD];
    __shared__ float NPs[3][DD];   // -P, for the second wedge term on the j side
    __shared__ float Qs[3][DD];

    const int tid = threadIdx.x;

    if (tid < DD) {
        const float p0 = p[tid];
        const float y1 = p[1 * DD + tid] - p0;
        const float y2 = p[2 * DD + tid] - p0;
        const float y3 = p[3 * DD + tid] - p0;
        const float y4 = p[4 * DD + tid] - p0;
        const float y5 = p[5 * DD + tid] - p0;
        const float y6 = p[6 * DD + tid] - p0;

        o[tid] = y6;  // level-1 term

        #pragma unroll
        for (int k = 0; k < 3; k++) {
            float Pk = fmaf(PA[k][0], y2, fmaf(PA[k][1], y4, PA[k][2] * y6));
            float Qk = fmaf(QB[k][0], y1, fmaf(QB[k][1], y3, QB[k][2] * y5));
            Ps[k][tid]  = Pk;
            NPs[k][tid] = -Pk;
            Qs[k][tid]  = Qk;
        }
    }
    __syncthreads();

    const int warp = tid >> 5;
    const int lane = tid & 31;

    // 95 pair-rows in 24 groups of 4; warp w takes groups w, w+8, w+16
    // (3/2/1 j-tiles per band -> 6 tiles per warp, balanced).
    for (int g = warp; g < 24; g += 8) {
        const int i0 = 4 * g;

        unsigned long long PPa[3], PPb[3], QQa[3], QQb[3];
        #pragma unroll
        for (int k = 0; k < 3; k++) {
            PPa[k] = pack2(Ps[k][i0],     Ps[k][i0 + 1]);
            PPb[k] = pack2(Ps[k][i0 + 2], Ps[k][i0 + 3]);
            QQa[k] = pack2(Qs[k][i0],     Qs[k][i0 + 1]);
            QQb[k] = pack2(Qs[k][i0 + 2], Qs[k][i0 + 3]);
        }

        // per-row output bases: row i starts at o + DD + i*95 - i(i-1)/2, entry (j-i-1)
        float* rb[4];
        #pragma unroll
        for (int r = 0; r < 4; r++) {
            const int i = i0 + r;
            rb[r] = o + DD + i * 95 - ((i * (i - 1)) >> 1) - i - 1;
        }

        const int jt0 = (i0 + 1) >> 5;
        for (int jt = jt0; jt < 3; jt++) {
            const int j = (jt << 5) + lane;

            unsigned long long acc_a, acc_b;
            {
                const unsigned long long qj  = pack2(Qs[0][j],  Qs[0][j]);
                const unsigned long long npj = pack2(NPs[0][j], NPs[0][j]);
                acc_a = mul2(PPa[0], qj);
                acc_b = mul2(PPb[0], qj);
                acc_a = fma2(QQa[0], npj, acc_a);
                acc_b = fma2(QQb[0], npj, acc_b);
            }
            #pragma unroll
            for (int k = 1; k < 3; k++) {
                const unsigned long long qj  = pack2(Qs[k][j],  Qs[k][j]);
                const unsigned long long npj = pack2(NPs[k][j], NPs[k][j]);
                acc_a = fma2(PPa[k], qj, acc_a);
                acc_b = fma2(PPb[k], qj, acc_b);
                acc_a = fma2(QQa[k], npj, acc_a);
                acc_b = fma2(QQb[k], npj, acc_b);
            }

            float v0, v1, v2, v3;
            unpack2(acc_a, v0, v1);
            unpack2(acc_b, v2, v3);

            if (j > i0)     rb[0][j] = v0;
            if (j > i0 + 1) rb[1][j] = v1;
            if (j > i0 + 2) rb[2][j] = v2;
            if (j > i0 + 3) rb[3][j] = v3;
        }
    }
}

extern "C" void kernel_launch(void* const* d_in, const int* in_sizes, int n_in,
                              void* d_out, int out_size)
{
    const float* inp = (const float*)d_in[0];
    float* out = (float*)d_out;
    logsig_kernel<<<BATCH * NSEG, 256>>>(inp, out);
}

// round 3
// speedup vs baseline: 1.4251x; 1.0104x over previous
#include <cuda_runtime.h>
#include <cuda_bf16.h>

#define DD 96
#define NSEG 50
#define NT 301
#define BATCH 256
#define OUTW 4656   // 96 + 96*95/2

// ---- Youla decomposition constants for the 6x6 antisymmetric tridiagonal form ----
#define S1d 0.4338837391175581204757683328483
#define S2d 0.7818314824680298087084445266741
#define S3d 0.9749279121818236070181316829939
#define C1d 0.9009688679024191262361023195074
#define C2d 0.6234898018587335305250048840042
#define C3d 0.2225209339563144042889025644968
// P_k = (cos(k pi/7)/1.75) * ( -sin(2k pi/7) y2 + sin(4k pi/7)... ) per table below
// A[i,j] = sum_k P_k[i] Q_k[j] - Q_k[i] P_k[j]
__device__ __constant__ float PA[3][3] = {
    { (float)(-(C1d/1.75)*S2d), (float)( (C1d/1.75)*S3d), (float)(-(C1d/1.75)*S1d) },
    { (float)(-(C2d/1.75)*S3d), (float)(-(C2d/1.75)*S1d), (float)( (C2d/1.75)*S2d) },
    { (float)(-(C3d/1.75)*S1d), (float)(-(C3d/1.75)*S2d), (float)(-(C3d/1.75)*S3d) },
};
__device__ __constant__ float QB[3][3] = {
    { (float)( S1d), (float)(-S3d), (float)( S2d) },
    { (float)( S2d), (float)(-S1d), (float)(-S3d) },
    { (float)( S3d), (float)( S2d), (float)( S1d) },
};

typedef unsigned long long u64;

__device__ __forceinline__ u64 pack2f(float lo, float hi) {
    u64 r;
    asm("mov.b64 %0, {%1, %2};" : "=l"(r) : "f"(lo), "f"(hi));
    return r;
}
__device__ __forceinline__ u64 packf2(float2 v) { return pack2f(v.x, v.y); }
__device__ __forceinline__ u64 fma2(u64 a, u64 b, u64 c) {
    u64 d;
    asm("fma.rn.f32x2 %0, %1, %2, %3;" : "=l"(d) : "l"(a), "l"(b), "l"(c));
    return d;
}
__device__ __forceinline__ u64 mul2(u64 a, u64 b) {
    u64 d;
    asm("mul.rn.f32x2 %0, %1, %2;" : "=l"(d) : "l"(a), "l"(b));
    return d;
}
__device__ __forceinline__ void unpack2(u64 v, float& lo, float& hi) {
    asm("mov.b64 {%0, %1}, %2;" : "=f"(lo), "=f"(hi) : "l"(v));
}

__global__ __launch_bounds__(256)
void logsig_kernel(const float* __restrict__ inp, float* __restrict__ out)
{
    const int bs = blockIdx.x;
    const int b  = bs / NSEG;
    const int s  = bs - b * NSEG;
    const float* __restrict__ p = inp + ((size_t)b * NT + 6 * s) * DD;
    float* __restrict__ o = out + (size_t)bs * OUTW;

    __shared__ float  Ps[3][DD];        // row-side packs (contiguous, LDS.64)
    __shared__ float  Qs[3][DD];
    __shared__ float2 Qdup[3][DD];      // j-side broadcast operands, pre-duplicated
    __shared__ float2 NPdup[3][DD];

    const int tid = threadIdx.x;

    if (tid < DD) {
        const float p0 = p[tid];
        const float y1 = p[1 * DD + tid] - p0;
        const float y2 = p[2 * DD + tid] - p0;
        const float y3 = p[3 * DD + tid] - p0;
        const float y4 = p[4 * DD + tid] - p0;
        const float y5 = p[5 * DD + tid] - p0;
        const float y6 = p[6 * DD + tid] - p0;

        o[tid] = y6;  // level-1 term

        #pragma unroll
        for (int k = 0; k < 3; k++) {
            float Pk = fmaf(PA[k][0], y2, fmaf(PA[k][1], y4, PA[k][2] * y6));
            float Qk = fmaf(QB[k][0], y1, fmaf(QB[k][1], y3, QB[k][2] * y5));
            Ps[k][tid]    = Pk;
            Qs[k][tid]    = Qk;
            Qdup[k][tid]  = make_float2(Qk, Qk);
            NPdup[k][tid] = make_float2(-Pk, -Pk);
        }
    }
    __syncthreads();

    const int warp = tid >> 5;
    const int lane = tid & 31;
    const int t4   = 4 * warp;   // boundary threshold: store row r iff lane > t4 + r

    // Band b: group i0 = 32*band + 4*warp, j-tiles jt = band..2.
    // Boundary tile is jt == band (j = 32*band + lane vs i = 32*band + 4w + r
    //  -> condition lane > 4w + r, band-independent).
    #pragma unroll
    for (int band = 0; band < 3; band++) {
        const int i0 = 32 * band + t4;

        // row-side packed operands (LDS.64, contiguous & 8B-aligned since i0 % 4 == 0)
        u64 PPa[3], PPb[3], QQa[3], QQb[3];
        #pragma unroll
        for (int k = 0; k < 3; k++) {
            PPa[k] = packf2(*(const float2*)&Ps[k][i0]);
            PPb[k] = packf2(*(const float2*)&Ps[k][i0 + 2]);
            QQa[k] = packf2(*(const float2*)&Qs[k][i0]);
            QQb[k] = packf2(*(const float2*)&Qs[k][i0 + 2]);
        }

        // per-row lane pointers; tile offsets become STG immediates
        float* rp[4];
        #pragma unroll
        for (int r = 0; r < 4; r++) {
            const int i = i0 + r;
            rp[r] = o + DD + i * 95 - ((i * (i - 1)) >> 1) - i - 1 + lane;
        }

        #pragma unroll
        for (int jt = band; jt < 3; jt++) {
            const int j = (jt << 5) + lane;

            u64 acc_a, acc_b;
            {
                const u64 qj  = packf2(Qdup[0][j]);
                const u64 npj = packf2(NPdup[0][j]);
                acc_a = mul2(PPa[0], qj);
                acc_b = mul2(PPb[0], qj);
                acc_a = fma2(QQa[0], npj, acc_a);
                acc_b = fma2(QQb[0], npj, acc_b);
            }
            #pragma unroll
            for (int k = 1; k < 3; k++) {
                const u64 qj  = packf2(Qdup[k][j]);
                const u64 npj = packf2(NPdup[k][j]);
                acc_a = fma2(PPa[k], qj, acc_a);
                acc_b = fma2(PPb[k], qj, acc_b);
                acc_a = fma2(QQa[k], npj, acc_a);
                acc_b = fma2(QQb[k], npj, acc_b);
            }

            float v0, v1, v2, v3;
            unpack2(acc_a, v0, v1);
            unpack2(acc_b, v2, v3);

            const int off = jt << 5;   // compile-time immediate after unroll
            if (jt == band) {          // boundary tile: mask left edge
                if (lane > t4)     rp[0][off] = v0;
                if (lane > t4 + 1) rp[1][off] = v1;
                if (lane > t4 + 2) rp[2][off] = v2;
                if (lane > t4 + 3) rp[3][off] = v3;
            } else {                   // interior: unconditional
                rp[0][off] = v0;
                rp[1][off] = v1;
                rp[2][off] = v2;
                rp[3][off] = v3;
            }
        }
    }
}

extern "C" void kernel_launch(void* const* d_in, const int* in_sizes, int n_in,
                              void* d_out, int out_size)
{
    const float* inp = (const float*)d_in[0];
    float* out = (float*)d_out;
    logsig_kernel<<<BATCH * NSEG, 256>>>(inp, out);
}

// round 4
// speedup vs baseline: 1.6010x; 1.1234x over previous
#include <cuda_runtime.h>
#include <cuda_bf16.h>

#define DD 96
#define NSEG 50
#define NT 301
#define BATCH 256
#define OUTW 4656          // 96 + 96*95/2
#define TILES_PB 8         // segments per block
#define GRID (BATCH * NSEG / TILES_PB)   // 1600

// ---- Youla decomposition of the 6x6 antisymmetric tridiagonal form ----
#define S1d 0.4338837391175581204757683328483
#define S2d 0.7818314824680298087084445266741
#define S3d 0.9749279121818236070181316829939
#define C1d 0.9009688679024191262361023195074
#define C2d 0.6234898018587335305250048840042
#define C3d 0.2225209339563144042889025644968
// A[i,j] = sum_k P_k[i] Q_k[j] - Q_k[i] P_k[j]
__device__ __constant__ float PA[3][3] = {
    { (float)(-(C1d/1.75)*S2d), (float)( (C1d/1.75)*S3d), (float)(-(C1d/1.75)*S1d) },
    { (float)(-(C2d/1.75)*S3d), (float)(-(C2d/1.75)*S1d), (float)( (C2d/1.75)*S2d) },
    { (float)(-(C3d/1.75)*S1d), (float)(-(C3d/1.75)*S2d), (float)(-(C3d/1.75)*S3d) },
};
__device__ __constant__ float QB[3][3] = {
    { (float)( S1d), (float)(-S3d), (float)( S2d) },
    { (float)( S2d), (float)(-S1d), (float)(-S3d) },
    { (float)( S3d), (float)( S2d), (float)( S1d) },
};

typedef unsigned long long u64;

__device__ __forceinline__ u64 pack2f(float lo, float hi) {
    u64 r; asm("mov.b64 %0, {%1, %2};" : "=l"(r) : "f"(lo), "f"(hi)); return r;
}
__device__ __forceinline__ u64 packf2(float2 v) { return pack2f(v.x, v.y); }
__device__ __forceinline__ u64 fma2(u64 a, u64 b, u64 c) {
    u64 d; asm("fma.rn.f32x2 %0, %1, %2, %3;" : "=l"(d) : "l"(a), "l"(b), "l"(c)); return d;
}
__device__ __forceinline__ u64 mul2(u64 a, u64 b) {
    u64 d; asm("mul.rn.f32x2 %0, %1, %2;" : "=l"(d) : "l"(a), "l"(b)); return d;
}
__device__ __forceinline__ void unpack2(u64 v, float& lo, float& hi) {
    asm("mov.b64 {%0, %1}, %2;" : "=f"(lo), "=f"(hi) : "l"(v));
}

__global__ __launch_bounds__(256)
void logsig_kernel(const float* __restrict__ inp, float* __restrict__ out)
{
    __shared__ float  Ps[2][3][DD];
    __shared__ float  Qs[2][3][DD];
    __shared__ float2 Qdup[2][3][DD];
    __shared__ float2 NPdup[2][3][DD];

    const int tid  = threadIdx.x;
    const int warp = tid >> 5;
    const int lane = tid & 31;
    const int t4   = 4 * warp;

    const int bs0 = blockIdx.x * TILES_PB;

    // ---- prefetch tile 0 inputs into registers ----
    float pf[7];
    if (tid < DD) {
        const int b = bs0 / NSEG, s = bs0 - b * NSEG;
        const float* __restrict__ p = inp + ((size_t)b * NT + 6 * s) * DD + tid;
        #pragma unroll
        for (int t = 0; t < 7; t++) pf[t] = p[t * DD];
    }

    int buf = 0;
    for (int it = 0; it < TILES_PB; it++) {
        const int bs = bs0 + it;
        float* __restrict__ o = out + (size_t)bs * OUTW;

        // ---- stage P/Q for this tile from prefetched registers ----
        if (tid < DD) {
            const float p0 = pf[0];
            const float y1 = pf[1] - p0, y2 = pf[2] - p0, y3 = pf[3] - p0;
            const float y4 = pf[4] - p0, y5 = pf[5] - p0, y6 = pf[6] - p0;
            o[tid] = y6;  // level-1 term
            #pragma unroll
            for (int k = 0; k < 3; k++) {
                float Pk = fmaf(PA[k][0], y2, fmaf(PA[k][1], y4, PA[k][2] * y6));
                float Qk = fmaf(QB[k][0], y1, fmaf(QB[k][1], y3, QB[k][2] * y5));
                Ps[buf][k][tid]    = Pk;
                Qs[buf][k][tid]    = Qk;
                Qdup[buf][k][tid]  = make_float2(Qk, Qk);
                NPdup[buf][k][tid] = make_float2(-Pk, -Pk);
            }
        }
        __syncthreads();

        // ---- issue prefetch for next tile (latency hidden behind compute) ----
        if (it + 1 < TILES_PB && tid < DD) {
            const int bs2 = bs + 1;
            const int b2 = bs2 / NSEG, s2 = bs2 - b2 * NSEG;
            const float* __restrict__ p2 = inp + ((size_t)b2 * NT + 6 * s2) * DD + tid;
            #pragma unroll
            for (int t = 0; t < 7; t++) pf[t] = p2[t * DD];
        }

        // ---- compute + store this tile ----
        // Band b: i0 = 32*band + 4*warp, j-tiles jt = band..2; boundary mask is
        // lane > 4w + r (band-independent).
        #pragma unroll
        for (int band = 0; band < 3; band++) {
            const int i0 = 32 * band + t4;

            u64 PPa[3], PPb[3], QQa[3], QQb[3];
            #pragma unroll
            for (int k = 0; k < 3; k++) {
                PPa[k] = packf2(*(const float2*)&Ps[buf][k][i0]);
                PPb[k] = packf2(*(const float2*)&Ps[buf][k][i0 + 2]);
                QQa[k] = packf2(*(const float2*)&Qs[buf][k][i0]);
                QQb[k] = packf2(*(const float2*)&Qs[buf][k][i0 + 2]);
            }

            float* rp[4];
            #pragma unroll
            for (int r = 0; r < 4; r++) {
                const int i = i0 + r;
                rp[r] = o + DD + i * 95 - ((i * (i - 1)) >> 1) - i - 1 + lane;
            }

            #pragma unroll
            for (int jt = band; jt < 3; jt++) {
                const int j = (jt << 5) + lane;

                u64 acc_a, acc_b;
                {
                    const u64 qj  = packf2(Qdup[buf][0][j]);
                    const u64 npj = packf2(NPdup[buf][0][j]);
                    acc_a = mul2(PPa[0], qj);
                    acc_b = mul2(PPb[0], qj);
                    acc_a = fma2(QQa[0], npj, acc_a);
                    acc_b = fma2(QQb[0], npj, acc_b);
                }
                #pragma unroll
                for (int k = 1; k < 3; k++) {
                    const u64 qj  = packf2(Qdup[buf][k][j]);
                    const u64 npj = packf2(NPdup[buf][k][j]);
                    acc_a = fma2(PPa[k], qj, acc_a);
                    acc_b = fma2(PPb[k], qj, acc_b);
                    acc_a = fma2(QQa[k], npj, acc_a);
                    acc_b = fma2(QQb[k], npj, acc_b);
                }

                float v0, v1, v2, v3;
                unpack2(acc_a, v0, v1);
                unpack2(acc_b, v2, v3);

                const int off = jt << 5;
                if (jt == band) {
                    if (lane > t4)     rp[0][off] = v0;
                    if (lane > t4 + 1) rp[1][off] = v1;
                    if (lane > t4 + 2) rp[2][off] = v2;
                    if (lane > t4 + 3) rp[3][off] = v3;
                } else {
                    rp[0][off] = v0;
                    rp[1][off] = v1;
                    rp[2][off] = v2;
                    rp[3][off] = v3;
                }
            }
        }

        buf ^= 1;
        // One barrier per iteration is sufficient with double buffering:
        // reads of buffer X at iter t precede the iter-(t+1) barrier, which
        // precedes the iter-(t+2) rewrite of X.
    }
}

extern "C" void kernel_launch(void* const* d_in, const int* in_sizes, int n_in,
                              void* d_out, int out_size)
{
    const float* inp = (const float*)d_in[0];
    float* out = (float*)d_out;
    logsig_kernel<<<GRID, 256>>>(inp, out);
}

// round 5
// speedup vs baseline: 1.6018x; 1.0005x over previous
#include <cuda_runtime.h>
#include <cuda_bf16.h>

#define DD 96
#define NSEG 50
#define NT 301
#define BATCH 256
#define OUTW 4656          // 96 + 96*95/2
#define TILES_PB 8
#define GRID (BATCH * NSEG / TILES_PB)   // 1600

// ---- Youla decomposition of the 6x6 antisymmetric tridiagonal form ----
#define S1d 0.4338837391175581204757683328483
#define S2d 0.7818314824680298087084445266741
#define S3d 0.9749279121818236070181316829939
#define C1d 0.9009688679024191262361023195074
#define C2d 0.6234898018587335305250048840042
#define C3d 0.2225209339563144042889025644968
// A[i,j] = sum_k P_k[i] Q_k[j] - Q_k[i] P_k[j]
__device__ __constant__ float PA[3][3] = {
    { (float)(-(C1d/1.75)*S2d), (float)( (C1d/1.75)*S3d), (float)(-(C1d/1.75)*S1d) },
    { (float)(-(C2d/1.75)*S3d), (float)(-(C2d/1.75)*S1d), (float)( (C2d/1.75)*S2d) },
    { (float)(-(C3d/1.75)*S1d), (float)(-(C3d/1.75)*S2d), (float)(-(C3d/1.75)*S3d) },
};
__device__ __constant__ float QB[3][3] = {
    { (float)( S1d), (float)(-S3d), (float)( S2d) },
    { (float)( S2d), (float)(-S1d), (float)(-S3d) },
    { (float)( S3d), (float)( S2d), (float)( S1d) },
};

typedef unsigned long long u64;

__device__ __forceinline__ u64 pack2f(float lo, float hi) {
    u64 r; asm("mov.b64 %0, {%1, %2};" : "=l"(r) : "f"(lo), "f"(hi)); return r;
}
__device__ __forceinline__ u64 fma2(u64 a, u64 b, u64 c) {
    u64 d; asm("fma.rn.f32x2 %0, %1, %2, %3;" : "=l"(d) : "l"(a), "l"(b), "l"(c)); return d;
}
__device__ __forceinline__ u64 mul2(u64 a, u64 b) {
    u64 d; asm("mul.rn.f32x2 %0, %1, %2;" : "=l"(d) : "l"(a), "l"(b)); return d;
}
__device__ __forceinline__ void unpack2(u64 v, float& lo, float& hi) {
    asm("mov.b64 {%0, %1}, %2;" : "=f"(lo), "=f"(hi) : "l"(v));
}

// smem buffers (double-buffered)
struct SBuf {
    float Ps[3][DD];
    float Qs[3][DD];
    float NPs[3][DD];
};

// Process one 8-row group (rows 8g..8g+7; this thread's half-warp handles
// rows 8g+4*half .. +3) over j-tiles jt = JTF..2; jt == JTF is the boundary
// tile (masked), the rest are interior (unconditional).
// Row classes by i mod 4 (= r): r=0,1 -> odd triangular base offset (2x STG.32),
// r=2,3 -> even offset (single STG.64 from packed accumulator).
template<int JTF>
__device__ __forceinline__ void do_group(int g, int half, int jl,
                                         const SBuf* __restrict__ sb,
                                         float* __restrict__ o)
{
    const int i0 = 8 * g + 4 * half;

    // row-side scalars
    float Pr[3][4], Qr[3][4];
    #pragma unroll
    for (int k = 0; k < 3; k++)
        #pragma unroll
        for (int r = 0; r < 4; r++) {
            Pr[k][r] = sb->Ps[k][i0 + r];
            Qr[k][r] = sb->Qs[k][i0 + r];
        }

    // lane-adjusted row base pointers (j offset 2*jl folded in; tile adds 32*jt)
    float* rb[4];
    #pragma unroll
    for (int r = 0; r < 4; r++) {
        const int i = i0 + r;
        rb[r] = o + DD + i * 95 - ((i * (i - 1)) >> 1) - i - 1 + 2 * jl;
    }

    #pragma unroll
    for (int jt = JTF; jt < 3; jt++) {
        u64 acc[4];
        #pragma unroll
        for (int k = 0; k < 3; k++) {
            const u64 qp  = *(const u64*)&sb->Qs[k][32 * jt + 2 * jl];
            const u64 npp = *(const u64*)&sb->NPs[k][32 * jt + 2 * jl];
            #pragma unroll
            for (int r = 0; r < 4; r++) {
                const u64 pd = pack2f(Pr[k][r], Pr[k][r]);
                const u64 qd = pack2f(Qr[k][r], Qr[k][r]);
                if (k == 0) acc[r] = mul2(pd, qp);
                else        acc[r] = fma2(pd, qp, acc[r]);
                acc[r] = fma2(qd, npp, acc[r]);
            }
        }

        const int off = 32 * jt;
        if (jt == JTF) {
            // boundary tile: mask against j > i
            const int j0 = 32 * JTF + 2 * jl;
            #pragma unroll
            for (int r = 0; r < 4; r++) {
                const int i = i0 + r;
                float lo, hi; unpack2(acc[r], lo, hi);
                if (r < 2) {                       // odd base offset rows
                    if (j0     > i) rb[r][off]     = lo;
                    if (j0 + 1 > i) rb[r][off + 1] = hi;
                } else {                           // even base offset rows
                    if (j0 > i)       *(u64*)&rb[r][off] = acc[r];
                    else if (j0 == i) rb[r][off + 1] = hi;
                }
            }
        } else {
            #pragma unroll
            for (int r = 0; r < 4; r++) {
                if (r < 2) {
                    float lo, hi; unpack2(acc[r], lo, hi);
                    rb[r][off]     = lo;
                    rb[r][off + 1] = hi;
                } else {
                    *(u64*)&rb[r][off] = acc[r];
                }
            }
        }
    }
}

__global__ __launch_bounds__(256, 3)
void logsig_kernel(const float* __restrict__ inp, float* __restrict__ out)
{
    __shared__ __align__(16) SBuf sb[2];

    const int tid  = threadIdx.x;
    const int warp = tid >> 5;
    const int lane = tid & 31;
    const int half = lane >> 4;
    const int jl   = lane & 15;

    const int bs0 = blockIdx.x * TILES_PB;

    // prefetch tile 0 inputs
    float pf[7];
    if (tid < DD) {
        const int b = bs0 / NSEG, s = bs0 - b * NSEG;
        const float* __restrict__ p = inp + ((size_t)b * NT + 6 * s) * DD + tid;
        #pragma unroll
        for (int t = 0; t < 7; t++) pf[t] = p[t * DD];
    }

    int buf = 0;
    for (int it = 0; it < TILES_PB; it++) {
        const int bs = bs0 + it;
        float* __restrict__ o = out + (size_t)bs * OUTW;

        // stage P/Q/NP from prefetched registers
        if (tid < DD) {
            const float p0 = pf[0];
            const float y1 = pf[1] - p0, y2 = pf[2] - p0, y3 = pf[3] - p0;
            const float y4 = pf[4] - p0, y5 = pf[5] - p0, y6 = pf[6] - p0;
            o[tid] = y6;  // level-1 term
            #pragma unroll
            for (int k = 0; k < 3; k++) {
                float Pk = fmaf(PA[k][0], y2, fmaf(PA[k][1], y4, PA[k][2] * y6));
                float Qk = fmaf(QB[k][0], y1, fmaf(QB[k][1], y3, QB[k][2] * y5));
                sb[buf].Ps[k][tid]  = Pk;
                sb[buf].Qs[k][tid]  = Qk;
                sb[buf].NPs[k][tid] = -Pk;
            }
        }
        __syncthreads();

        // prefetch next tile (latency hidden behind compute)
        if (it + 1 < TILES_PB && tid < DD) {
            const int bs2 = bs + 1;
            const int b2 = bs2 / NSEG, s2 = bs2 - b2 * NSEG;
            const float* __restrict__ p2 = inp + ((size_t)b2 * NT + 6 * s2) * DD + tid;
            #pragma unroll
            for (int t = 0; t < 7; t++) pf[t] = p2[t * DD];
        }

        // compute + store: 12 groups of 8 rows, 24 warp-tiles, 3 per warp
        const SBuf* sp = &sb[buf];
        if (warp < 4) {
            do_group<0>(warp, half, jl, sp, o);          // groups 0-3: jt 0,1,2
        } else {
            do_group<1>(warp, half, jl, sp, o);          // groups 4-7: jt 1,2
            do_group<2>(warp + 4, half, jl, sp, o);      // groups 8-11: jt 2
        }

        buf ^= 1;
        // one barrier per iteration suffices with double buffering
    }
}

extern "C" void kernel_launch(void* const* d_in, const int* in_sizes, int n_in,
                              void* d_out, int out_size)
{
    const float* inp = (const float*)d_in[0];
    float* out = (float*)d_out;
    logsig_kernel<<<GRID, 256>>>(inp, out);
}